// round 9
// baseline (speedup 1.0000x reference)
#include <cuda_runtime.h>
#include <cstdint>
#include <cstddef>

#define BB 4
#define TT 32
#define NN 1024
#define KK 16
#define HD 128

// d_out layout (float32, concatenated outputs):
//   out1: [B][T][132][N]      17,301,504
//   h:    [B][128][N]            524,288   @ 17,301,504
//   c:    [B][128][N]            524,288   @ 17,825,792
//   gidx: [B][T][N][K] (cast)  2,097,152   @ 18,350,080
#define OFF_H 17301504
#define OFF_C 17825792
#define OFF_I 18350080

#define SBT   (BB*NN*HD)     // per-timestep h/c slab: 524288 floats
#define VSLAB ((size_t)BB*NN*512)  // per-timestep V slab: 2M floats

// ---------------- device scratch (static, allowed) ----------------
__device__ float g_U[BB*NN*512];
__device__ float g_V0[(size_t)TT*VSLAB];      // 256 MB: V layer0, all t
__device__ float g_V1[(size_t)TT*VSLAB];      // 256 MB: V layer1, all t
__device__ float g_hs0[(size_t)TT*BB*NN*HD];  // [t][b][n][j]
__device__ float g_hs1[(size_t)TT*BB*NN*HD];
__device__ float g_c[2][BB*NN*HD];            // ping-pong, [b][n][j]
__device__ int   g_idx[BB*TT*NN*KK];
__device__ float g_Wd0[512*4];
__device__ float g_Wd1[512*4];

// ---------------- fast math helpers ----------------
__device__ __forceinline__ float sigf(float x) {
    return __fdividef(1.0f, 1.0f + __expf(-x));
}

// ---------------- KNN: stable top-16 smallest d2 ----------------
// Rounding matches XLA's fp32 emission:
//   q2/r2: separate mul + add ops (NO fma contraction)
//   qr:    fma accumulation chain from 0
//   d2:    fl( fl(q2 + r2) - 2*qr )
__global__ __launch_bounds__(256) void knn_kernel(const float* __restrict__ x) {
    __shared__ float rx[NN], ry[NN], rz[NN], rr[NN];
    int t = blockIdx.y, b = blockIdx.z;
    int f = t ? t - 1 : 0;
    const float* rb = x + ((size_t)(b*TT + f) * 4) * NN;
    for (int i = threadIdx.x; i < NN; i += 256) {
        float a = rb[i], bb = rb[NN + i], cc = rb[2*NN + i];
        rx[i] = a; ry[i] = bb; rz[i] = cc;
        float s = __fadd_rn(__fmul_rn(a, a), __fmul_rn(bb, bb));
        rr[i] = __fadd_rn(s, __fmul_rn(cc, cc));
    }
    __syncthreads();

    int n = blockIdx.x * 256 + threadIdx.x;
    const float* qb = x + ((size_t)(b*TT + t) * 4) * NN;
    float qx = qb[n], qy = qb[NN + n], qz = qb[2*NN + n];
    float q2 = __fadd_rn(__fadd_rn(__fmul_rn(qx, qx), __fmul_rn(qy, qy)),
                         __fmul_rn(qz, qz));

    float bd[KK]; int bi[KK];
#pragma unroll
    for (int k = 0; k < KK; ++k) { bd[k] = 3.402823466e38f; bi[k] = 0; }

    for (int m = 0; m < NN; ++m) {
        float qr = __fmaf_rn(qz, rz[m],
                    __fmaf_rn(qy, ry[m],
                     __fmaf_rn(qx, rx[m], 0.0f)));
        float d  = __fsub_rn(__fadd_rn(q2, rr[m]), __fmul_rn(2.0f, qr));
        if (d < bd[KK-1]) {
            bd[KK-1] = d; bi[KK-1] = m;
#pragma unroll
            for (int jj = KK-1; jj > 0; --jj) {
                if (bd[jj] < bd[jj-1]) {
                    float td = bd[jj]; bd[jj] = bd[jj-1]; bd[jj-1] = td;
                    int   ti = bi[jj]; bi[jj] = bi[jj-1]; bi[jj-1] = ti;
                }
            }
        }
    }
    int* op = g_idx + (((size_t)b*TT + t) * NN + n) * KK;
#pragma unroll
    for (int k = 0; k < KK; ++k) op[k] = bi[k];
}

// ---------------- weight prep: Wd = Wx[:, :4] - Wpd ----------------
__global__ void wdiff_kernel(const float* __restrict__ w0, const float* __restrict__ w1) {
    int o = blockIdx.x * 128 + threadIdx.x;
    if (o < 512) {
#pragma unroll
        for (int c = 0; c < 4; ++c) {
            g_Wd0[o*4 + c] = w0[o*136 + c] - w0[o*136 + 4 + c];
            g_Wd1[o*4 + c] = w1[o*264 + c] - w1[o*264 + 132 + c];
        }
    }
}

// ---------------- GEMM: Out[b][m][o] = Wp(4ch)*pos + Wh(128ch)*H + bias ----
// Tile 64o x 64m, 256 threads, thread = 4o x 4m.
// modes: 0 = U layer0 (per t), 2 = U layer1 (per t),
//        4 = V0 batch (all t, pos-only), 5 = V1 batch (all t)
__global__ __launch_bounds__(256) void gemm_kernel(
    int mode, int t,
    const float* __restrict__ x,
    const float* __restrict__ w0, const float* __restrict__ b0,
    const float* __restrict__ w1, const float* __restrict__ b1)
{
    int b, tt;
    if (mode >= 4) { b = blockIdx.z & 3; tt = blockIdx.z >> 2; }
    else           { b = blockIdx.z;     tt = t; }

    const float* Wp;  int ldp;
    const float* Wh = nullptr; int ldh = 0;
    const float* bias = nullptr;
    const float* H = nullptr;
    float* Out;
    int frame;
    if (mode == 0) {
        Wp = w0 + 4; ldp = 136; Wh = w0 + 8; ldh = 136;
        frame = tt ? tt - 1 : 0;
        H = tt ? (g_hs0 + (size_t)(tt-1) * SBT) : nullptr;
        Out = g_U;
    } else if (mode == 2) {
        Wp = w1 + 132; ldp = 264; Wh = w1 + 136; ldh = 264;
        frame = tt ? tt - 1 : 0;
        H = tt ? (g_hs1 + (size_t)(tt-1) * SBT) : nullptr;
        Out = g_U;
    } else if (mode == 4) {
        Wp = g_Wd0; ldp = 4; bias = b0; frame = tt;
        Out = g_V0 + (size_t)tt * VSLAB;
    } else {
        Wp = g_Wd1; ldp = 4; Wh = w1 + 4; ldh = 264; bias = b1;
        frame = tt; H = g_hs0 + (size_t)tt * SBT;
        Out = g_V1 + (size_t)tt * VSLAB;
    }

    __shared__ float sWp[4][64];
    __shared__ float sP [4][64];
    __shared__ float sW [16][68];
    __shared__ float sIn[16][68];

    int tid = threadIdx.x;
    int o0  = blockIdx.x * 64;
    int m0  = blockIdx.y * 64;
    int of  = (tid & 15) * 4;   // 4 outputs per thread
    int mf  = (tid >> 4) * 4;   // 4 points per thread

    const float* Pb = x + ((size_t)(b*TT + frame) * 4) * NN + m0;
    {
        int c = tid >> 6, mm = tid & 63;
        sP[c][mm]  = Pb[(size_t)c * NN + mm];
        sWp[c][mm] = Wp[(size_t)(o0 + mm) * ldp + c];
    }
    __syncthreads();

    float acc[4][4];
    {
        float bv0 = 0.f, bv1 = 0.f, bv2 = 0.f, bv3 = 0.f;
        if (bias) { bv0 = bias[o0+of]; bv1 = bias[o0+of+1]; bv2 = bias[o0+of+2]; bv3 = bias[o0+of+3]; }
#pragma unroll
        for (int mi = 0; mi < 4; ++mi) { acc[mi][0]=bv0; acc[mi][1]=bv1; acc[mi][2]=bv2; acc[mi][3]=bv3; }
    }

    // position (4-channel) contribution
#pragma unroll
    for (int c = 0; c < 4; ++c) {
        float a0 = sWp[c][of], a1 = sWp[c][of+1], a2 = sWp[c][of+2], a3 = sWp[c][of+3];
#pragma unroll
        for (int mi = 0; mi < 4; ++mi) {
            float p = sP[c][mf + mi];
            acc[mi][0] = fmaf(a0, p, acc[mi][0]);
            acc[mi][1] = fmaf(a1, p, acc[mi][1]);
            acc[mi][2] = fmaf(a2, p, acc[mi][2]);
            acc[mi][3] = fmaf(a3, p, acc[mi][3]);
        }
    }

    // hidden (128-channel) contribution; H layout [b][m][j] (j contiguous)
    if (Wh && H) {
        const float* Hb = H + ((size_t)b * NN + m0) * HD;
        int rr4 = tid >> 2;          // 0..63
        int k4  = (tid & 3) * 4;     // 0,4,8,12
        for (int k0 = 0; k0 < HD; k0 += 16) {
            {   // W tile: 64 o x 16 k
                float4 wv = *reinterpret_cast<const float4*>(Wh + (size_t)(o0 + rr4) * ldh + k0 + k4);
                sW[k4  ][rr4] = wv.x; sW[k4+1][rr4] = wv.y;
                sW[k4+2][rr4] = wv.z; sW[k4+3][rr4] = wv.w;
            }
            {   // In tile (transposed load): 16 k x 64 m
                float4 hv = *reinterpret_cast<const float4*>(Hb + (size_t)rr4 * HD + k0 + k4);
                sIn[k4  ][rr4] = hv.x; sIn[k4+1][rr4] = hv.y;
                sIn[k4+2][rr4] = hv.z; sIn[k4+3][rr4] = hv.w;
            }
            __syncthreads();
#pragma unroll
            for (int k = 0; k < 16; ++k) {
                float4 a = *reinterpret_cast<const float4*>(&sW[k][of]);
                float4 p = *reinterpret_cast<const float4*>(&sIn[k][mf]);
                float pb[4] = {p.x, p.y, p.z, p.w};
#pragma unroll
                for (int mi = 0; mi < 4; ++mi) {
                    acc[mi][0] = fmaf(a.x, pb[mi], acc[mi][0]);
                    acc[mi][1] = fmaf(a.y, pb[mi], acc[mi][1]);
                    acc[mi][2] = fmaf(a.z, pb[mi], acc[mi][2]);
                    acc[mi][3] = fmaf(a.w, pb[mi], acc[mi][3]);
                }
            }
            __syncthreads();
        }
    }

    float* Ob = Out + ((size_t)b * NN + m0 + mf) * 512 + o0 + of;
#pragma unroll
    for (int mi = 0; mi < 4; ++mi) {
        float4 v = make_float4(acc[mi][0], acc[mi][1], acc[mi][2], acc[mi][3]);
        *reinterpret_cast<float4*>(Ob + (size_t)mi * 512) = v;
    }
}

// ---------------- gate + max-over-K ----------------
// One warp per point; each lane owns 4 consecutive j (float4 loads).
// Activations use combined denominators (8 MUFU/elem instead of 10):
//   sig(gi)*tanh(gg) = (1-b) / ((1+a)(1+b)),  a=e^-gi, b=e^-2gg
//   sig(go)*tanh(cn) = (1-d) / ((1+c)(1+d)),  c=e^-go, d=e^-2cn
__device__ __forceinline__ void gate4(
    float gi, float gf, float go, float gg, float cg,
    float& cn_out, float& hn_out)
{
    float ea = __expf(fminf(-gi, 80.f));
    float eb = __expf(fminf(-2.0f*gg, 80.f));
    float it = __fdividef(1.0f - eb, (1.0f + ea) * (1.0f + eb));
    float cn = fmaf(sigf(gf), cg, it);
    float ec = __expf(fminf(-go, 80.f));
    float ed = __expf(fminf(-2.0f*cn, 80.f));
    float hn = __fdividef(1.0f - ed, (1.0f + ec) * (1.0f + ed));
    cn_out = cn; hn_out = hn;
}

__global__ __launch_bounds__(256) void gate_kernel(int t, int layer) {
    int w = threadIdx.x >> 5, lane = threadIdx.x & 31;
    int n = blockIdx.x * 8 + w, b = blockIdx.y;
    __shared__ int sm[8][KK];
    if (lane < KK) sm[w][lane] = g_idx[(((size_t)b*TT + t) * NN + n) * KK + lane];
    __syncwarp();

    const float* Vp = (layer ? g_V1 : g_V0) + (size_t)t * VSLAB
                      + ((size_t)b * NN + n) * 512 + lane * 4;
    float4 v0 = *reinterpret_cast<const float4*>(Vp);
    float4 v1 = *reinterpret_cast<const float4*>(Vp + 128);
    float4 v2 = *reinterpret_cast<const float4*>(Vp + 256);
    float4 v3 = *reinterpret_cast<const float4*>(Vp + 384);
    const float* Cprev = t ? g_c[(t-1) & 1] : nullptr;

    float4 hmax = make_float4(-1e30f,-1e30f,-1e30f,-1e30f);
    float4 cmax = hmax;
#pragma unroll 4
    for (int k = 0; k < KK; ++k) {
        int m = sm[w][k];
        const float* Up = g_U + ((size_t)b * NN + m) * 512 + lane * 4;
        float4 u0 = *reinterpret_cast<const float4*>(Up);
        float4 u1 = *reinterpret_cast<const float4*>(Up + 128);
        float4 u2 = *reinterpret_cast<const float4*>(Up + 256);
        float4 u3 = *reinterpret_cast<const float4*>(Up + 384);
        float4 cg = make_float4(0.f,0.f,0.f,0.f);
        if (Cprev) cg = *reinterpret_cast<const float4*>(
                        Cprev + ((size_t)b * NN + m) * HD + lane * 4);
        float cn, hn;
        gate4(v0.x+u0.x, v1.x+u1.x, v2.x+u2.x, v3.x+u3.x, cg.x, cn, hn);
        cmax.x = fmaxf(cmax.x, cn); hmax.x = fmaxf(hmax.x, hn);
        gate4(v0.y+u0.y, v1.y+u1.y, v2.y+u2.y, v3.y+u3.y, cg.y, cn, hn);
        cmax.y = fmaxf(cmax.y, cn); hmax.y = fmaxf(hmax.y, hn);
        gate4(v0.z+u0.z, v1.z+u1.z, v2.z+u2.z, v3.z+u3.z, cg.z, cn, hn);
        cmax.z = fmaxf(cmax.z, cn); hmax.z = fmaxf(hmax.z, hn);
        gate4(v0.w+u0.w, v1.w+u1.w, v2.w+u2.w, v3.w+u3.w, cg.w, cn, hn);
        cmax.w = fmaxf(cmax.w, cn); hmax.w = fmaxf(hmax.w, hn);
    }
    size_t o = ((size_t)b * NN + n) * HD + lane * 4;
    float* Hout = (layer ? g_hs1 : g_hs0) + (size_t)t * SBT;
    *reinterpret_cast<float4*>(Hout + o) = hmax;
    *reinterpret_cast<float4*>(&g_c[t & 1][0] + o) = cmax;
}

// ---------------- output assembly ----------------
__global__ void out1_pos_kernel(const float* __restrict__ x, float* __restrict__ out) {
    int i = blockIdx.x * 256 + threadIdx.x;  // B*T*4*N = 524288
    if (i < BB*TT*4*NN) {
        int bt = i >> 12;
        int r  = i & 4095;
        out[(size_t)bt * 132 * NN + r] = x[i];
    }
}

__global__ void out1_hs_kernel(float* __restrict__ out) {
    __shared__ float tile[32][33];
    int n0 = blockIdx.x * 32, j0 = blockIdx.y * 32, bt = blockIdx.z;
    int b = bt >> 5, t = bt & 31;
    int tx = threadIdx.x, ty = threadIdx.y;
    tile[ty][tx] = g_hs1[(((size_t)t*BB + b) * NN + n0 + ty) * HD + j0 + tx];
    __syncthreads();
    out[((size_t)bt * 132 + 4 + j0 + ty) * NN + n0 + tx] = tile[tx][ty];
}

__global__ void hc_kernel(float* __restrict__ out) {
    __shared__ float th[32][33];
    __shared__ float tc[32][33];
    int n0 = blockIdx.x * 32, j0 = blockIdx.y * 32, b = blockIdx.z;
    int tx = threadIdx.x, ty = threadIdx.y;
    th[ty][tx] = g_hs1[(((size_t)(TT-1)*BB + b) * NN + n0 + ty) * HD + j0 + tx];
    tc[ty][tx] = g_c[(TT-1) & 1][((size_t)b * NN + n0 + ty) * HD + j0 + tx];
    __syncthreads();
    size_t dst = ((size_t)b * HD + j0 + ty) * NN + n0 + tx;
    out[OFF_H + dst] = th[tx][ty];
    out[OFF_C + dst] = tc[tx][ty];
}

__global__ void idxf_kernel(float* __restrict__ out) {
    int i = blockIdx.x * 256 + threadIdx.x;  // 2,097,152
    out[OFF_I + i] = (float)g_idx[i];
}

// ---------------- launch ----------------
extern "C" void kernel_launch(void* const* d_in, const int* in_sizes, int n_in,
                              void* d_out, int out_size) {
    const float* x  = (const float*)d_in[0];
    const float* w0 = (const float*)d_in[1];
    const float* b0 = (const float*)d_in[2];
    const float* w1 = (const float*)d_in[3];
    const float* b1 = (const float*)d_in[4];
    float* out = (float*)d_out;

    knn_kernel<<<dim3(4, TT, BB), 256>>>(x);
    wdiff_kernel<<<4, 128>>>(w0, w1);

    dim3 gu(8, 16, BB);        // per-t U gemm: 512 blocks
    dim3 gv(8, 16, BB*TT);     // batched V gemm: 16384 blocks
    dim3 gt(NN/8, BB);         // gate: warp per point

    gemm_kernel<<<gv, 256>>>(4, 0, x, w0, b0, w1, b1);      // V0, all t
    for (int t = 0; t < TT; ++t) {                          // layer 0
        gemm_kernel<<<gu, 256>>>(0, t, x, w0, b0, w1, b1);  // U0(t)
        gate_kernel<<<gt, 256>>>(t, 0);
    }
    gemm_kernel<<<gv, 256>>>(5, 0, x, w0, b0, w1, b1);      // V1, all t
    for (int t = 0; t < TT; ++t) {                          // layer 1
        gemm_kernel<<<gu, 256>>>(2, t, x, w0, b0, w1, b1);  // U1(t)
        gate_kernel<<<gt, 256>>>(t, 1);
    }

    out1_pos_kernel<<<2048, 256>>>(x, out);
    out1_hs_kernel<<<dim3(32, 4, BB*TT), dim3(32, 32)>>>(out);
    hc_kernel<<<dim3(32, 4, BB), dim3(32, 32)>>>(out);
    idxf_kernel<<<8192, 256>>>(out);
}

// round 10
// speedup vs baseline: 1.5291x; 1.5291x over previous
#include <cuda_runtime.h>
#include <cstdint>
#include <cstddef>

#define BB 4
#define TT 32
#define NN 1024
#define KK 16
#define HD 128

// d_out layout (float32, concatenated outputs):
//   out1: [B][T][132][N]      17,301,504
//   h:    [B][128][N]            524,288   @ 17,301,504
//   c:    [B][128][N]            524,288   @ 17,825,792
//   gidx: [B][T][N][K] (cast)  2,097,152   @ 18,350,080
#define OFF_H 17301504
#define OFF_C 17825792
#define OFF_I 18350080

#define SBT   (BB*NN*HD)           // per-timestep h/c slab: 524288 floats
#define VSLAB ((size_t)BB*NN*512)  // per-timestep V slab: 2M floats
#define NBLK  256                  // persistent grid size (co-resident: 2/SM x 148 SM >= 256)

// ---------------- device scratch (static, allowed) ----------------
__device__ float g_U[BB*NN*512];
__device__ float g_V0[(size_t)TT*VSLAB];      // V layer0, all t
__device__ float g_V1[(size_t)TT*VSLAB];      // V layer1, all t
__device__ float g_hs0[(size_t)TT*BB*NN*HD];  // [t][b][n][j]
__device__ float g_hs1[(size_t)TT*BB*NN*HD];
__device__ float g_c[2][BB*NN*HD];            // ping-pong, [b][n][j]
__device__ int   g_idx[BB*TT*NN*KK];
__device__ float g_Wd0[512*4];
__device__ float g_Wd1[512*4];

// ---------------- software grid barrier ----------------
__device__ unsigned g_bar_cnt = 0;
__device__ volatile unsigned g_bar_gen = 0;

__device__ __forceinline__ void grid_barrier() {
    __threadfence();          // flush this thread's global writes
    __syncthreads();
    if (threadIdx.x == 0) {
        unsigned gen = g_bar_gen;
        if (atomicAdd(&g_bar_cnt, 1) == (unsigned)(gridDim.x - 1)) {
            g_bar_cnt = 0;
            __threadfence();
            g_bar_gen = gen + 1;   // release
        } else {
            while (g_bar_gen == gen) __nanosleep(64);
        }
    }
    __syncthreads();
}

// ---------------- fast math helpers ----------------
__device__ __forceinline__ float sigf(float x) {
    return __fdividef(1.0f, 1.0f + __expf(-x));
}

// Combined-denominator gate activations (8 MUFU/elem):
//   sig(gi)*tanh(gg) = (1-b)/((1+a)(1+b)),  a=e^-gi, b=e^-2gg
__device__ __forceinline__ void gate4(
    float gi, float gf, float go, float gg, float cg,
    float& cn_out, float& hn_out)
{
    float ea = __expf(fminf(-gi, 80.f));
    float eb = __expf(fminf(-2.0f*gg, 80.f));
    float it = __fdividef(1.0f - eb, (1.0f + ea) * (1.0f + eb));
    float cn = fmaf(sigf(gf), cg, it);
    float ec = __expf(fminf(-go, 80.f));
    float ed = __expf(fminf(-2.0f*cn, 80.f));
    float hn = __fdividef(1.0f - ed, (1.0f + ec) * (1.0f + ed));
    cn_out = cn; hn_out = hn;
}

// ---------------- KNN: stable top-16 smallest d2 ----------------
// Rounding matches XLA's fp32 emission:
//   q2/r2: separate mul + add (NO fma contraction); qr: fma chain from 0;
//   d2: fl( fl(q2 + r2) - 2*qr )
__global__ __launch_bounds__(256) void knn_kernel(const float* __restrict__ x) {
    __shared__ float rx[NN], ry[NN], rz[NN], rr[NN];
    int t = blockIdx.y, b = blockIdx.z;
    int f = t ? t - 1 : 0;
    const float* rb = x + ((size_t)(b*TT + f) * 4) * NN;
    for (int i = threadIdx.x; i < NN; i += 256) {
        float a = rb[i], bb = rb[NN + i], cc = rb[2*NN + i];
        rx[i] = a; ry[i] = bb; rz[i] = cc;
        float s = __fadd_rn(__fmul_rn(a, a), __fmul_rn(bb, bb));
        rr[i] = __fadd_rn(s, __fmul_rn(cc, cc));
    }
    __syncthreads();

    int n = blockIdx.x * 256 + threadIdx.x;
    const float* qb = x + ((size_t)(b*TT + t) * 4) * NN;
    float qx = qb[n], qy = qb[NN + n], qz = qb[2*NN + n];
    float q2 = __fadd_rn(__fadd_rn(__fmul_rn(qx, qx), __fmul_rn(qy, qy)),
                         __fmul_rn(qz, qz));

    float bd[KK]; int bi[KK];
#pragma unroll
    for (int k = 0; k < KK; ++k) { bd[k] = 3.402823466e38f; bi[k] = 0; }

    for (int m = 0; m < NN; ++m) {
        float qr = __fmaf_rn(qz, rz[m],
                    __fmaf_rn(qy, ry[m],
                     __fmaf_rn(qx, rx[m], 0.0f)));
        float d  = __fsub_rn(__fadd_rn(q2, rr[m]), __fmul_rn(2.0f, qr));
        if (d < bd[KK-1]) {
            bd[KK-1] = d; bi[KK-1] = m;
#pragma unroll
            for (int jj = KK-1; jj > 0; --jj) {
                if (bd[jj] < bd[jj-1]) {
                    float td = bd[jj]; bd[jj] = bd[jj-1]; bd[jj-1] = td;
                    int   ti = bi[jj]; bi[jj] = bi[jj-1]; bi[jj-1] = ti;
                }
            }
        }
    }
    int* op = g_idx + (((size_t)b*TT + t) * NN + n) * KK;
#pragma unroll
    for (int k = 0; k < KK; ++k) op[k] = bi[k];
}

// ---------------- weight prep: Wd = Wx[:, :4] - Wpd ----------------
__global__ void wdiff_kernel(const float* __restrict__ w0, const float* __restrict__ w1) {
    int o = blockIdx.x * 128 + threadIdx.x;
    if (o < 512) {
#pragma unroll
        for (int c = 0; c < 4; ++c) {
            g_Wd0[o*4 + c] = w0[o*136 + c] - w0[o*136 + 4 + c];
            g_Wd1[o*4 + c] = w1[o*264 + c] - w1[o*264 + 132 + c];
        }
    }
}

// ---------------- batched V GEMM (independent of recurrence) ----------------
// mode 0: V0 = Wd0*pos + b0 (pos only);  mode 1: V1 = Wd1*pos + Wh*hs0(t) + b1
__global__ __launch_bounds__(256) void vgemm_kernel(
    int mode,
    const float* __restrict__ x,
    const float* __restrict__ b0,
    const float* __restrict__ w1, const float* __restrict__ b1)
{
    int b = blockIdx.z & 3, tt = blockIdx.z >> 2;

    const float* Wp   = mode ? g_Wd1 : g_Wd0;
    const float* bias = mode ? b1 : b0;
    const float* Wh   = mode ? (w1 + 4) : nullptr;
    int ldh           = 264;
    const float* H    = mode ? (g_hs0 + (size_t)tt * SBT) : nullptr;
    float* Out        = (mode ? g_V1 : g_V0) + (size_t)tt * VSLAB;

    __shared__ float sWp[4][64];
    __shared__ float sP [4][64];
    __shared__ float sW [16][68];
    __shared__ float sIn[16][68];

    int tid = threadIdx.x;
    int o0  = blockIdx.x * 64;
    int m0  = blockIdx.y * 64;
    int of  = (tid & 15) * 4;
    int mf  = (tid >> 4) * 4;

    const float* Pb = x + ((size_t)(b*TT + tt) * 4) * NN + m0;
    {
        int c = tid >> 6, mm = tid & 63;
        sP[c][mm]  = Pb[(size_t)c * NN + mm];
        sWp[c][mm] = Wp[(size_t)(o0 + mm) * 4 + c];
    }
    __syncthreads();

    float acc[4][4];
    {
        float bv0 = bias[o0+of], bv1 = bias[o0+of+1], bv2 = bias[o0+of+2], bv3 = bias[o0+of+3];
#pragma unroll
        for (int mi = 0; mi < 4; ++mi) { acc[mi][0]=bv0; acc[mi][1]=bv1; acc[mi][2]=bv2; acc[mi][3]=bv3; }
    }

#pragma unroll
    for (int c = 0; c < 4; ++c) {
        float a0 = sWp[c][of], a1 = sWp[c][of+1], a2 = sWp[c][of+2], a3 = sWp[c][of+3];
#pragma unroll
        for (int mi = 0; mi < 4; ++mi) {
            float p = sP[c][mf + mi];
            acc[mi][0] = fmaf(a0, p, acc[mi][0]);
            acc[mi][1] = fmaf(a1, p, acc[mi][1]);
            acc[mi][2] = fmaf(a2, p, acc[mi][2]);
            acc[mi][3] = fmaf(a3, p, acc[mi][3]);
        }
    }

    if (Wh && H) {
        const float* Hb = H + ((size_t)b * NN + m0) * HD;
        int rr4 = tid >> 2;
        int k4  = (tid & 3) * 4;
        for (int k0 = 0; k0 < HD; k0 += 16) {
            {
                float4 wv = *reinterpret_cast<const float4*>(Wh + (size_t)(o0 + rr4) * ldh + k0 + k4);
                sW[k4  ][rr4] = wv.x; sW[k4+1][rr4] = wv.y;
                sW[k4+2][rr4] = wv.z; sW[k4+3][rr4] = wv.w;
            }
            {
                float4 hv = *reinterpret_cast<const float4*>(Hb + (size_t)rr4 * HD + k0 + k4);
                sIn[k4  ][rr4] = hv.x; sIn[k4+1][rr4] = hv.y;
                sIn[k4+2][rr4] = hv.z; sIn[k4+3][rr4] = hv.w;
            }
            __syncthreads();
#pragma unroll
            for (int k = 0; k < 16; ++k) {
                float4 a = *reinterpret_cast<const float4*>(&sW[k][of]);
                float4 p = *reinterpret_cast<const float4*>(&sIn[k][mf]);
                float pb[4] = {p.x, p.y, p.z, p.w};
#pragma unroll
                for (int mi = 0; mi < 4; ++mi) {
                    acc[mi][0] = fmaf(a.x, pb[mi], acc[mi][0]);
                    acc[mi][1] = fmaf(a.y, pb[mi], acc[mi][1]);
                    acc[mi][2] = fmaf(a.z, pb[mi], acc[mi][2]);
                    acc[mi][3] = fmaf(a.w, pb[mi], acc[mi][3]);
                }
            }
            __syncthreads();
        }
    }

    float* Ob = Out + ((size_t)b * NN + m0 + mf) * 512 + o0 + of;
#pragma unroll
    for (int mi = 0; mi < 4; ++mi) {
        float4 v = make_float4(acc[mi][0], acc[mi][1], acc[mi][2], acc[mi][3]);
        *reinterpret_cast<float4*>(Ob + (size_t)mi * 512) = v;
    }
}

// ---------------- persistent per-layer kernel: full 32-step recurrence ------
// Phase A: U[b][m][o] = Wp*pos + Wh*h_prev   (512 tiles of 64o x 64m)
// Phase B: gate + max-over-K                  (4096 points, 1 warp each)
// Cross-step / cross-block mutable data read via __ldcg (L2-coherent).
__global__ __launch_bounds__(256, 2) void layer_kernel(
    int layer, const float* __restrict__ x,
    const float* __restrict__ w0, const float* __restrict__ w1)
{
    const float* Wp = layer ? (w1 + 132) : (w0 + 4);
    const float* Wh = layer ? (w1 + 136) : (w0 + 8);
    const int    ldw = layer ? 264 : 136;
    const float* Vbase = layer ? g_V1 : g_V0;
    float*       Hs    = layer ? g_hs1 : g_hs0;

    __shared__ float sWp[4][64];
    __shared__ float sP [4][64];
    __shared__ float sW [16][68];
    __shared__ float sIn[16][68];

    int tid  = threadIdx.x;
    int warp = tid >> 5, lane = tid & 31;

    for (int t = 0; t < TT; ++t) {
        int frame = t ? t - 1 : 0;
        const float* Hprev = t ? (Hs + (size_t)(t-1) * SBT) : nullptr;

        // ---------------- Phase A: U ----------------
        for (int tau = blockIdx.x; tau < 512; tau += NBLK) {
            int o0 = (tau & 7) * 64;
            int m0 = ((tau >> 3) & 15) * 64;
            int b  = tau >> 7;
            int of = (tid & 15) * 4;
            int mf = (tid >> 4) * 4;

            const float* Pb = x + ((size_t)(b*TT + frame) * 4) * NN + m0;
            {
                int c = tid >> 6, mm = tid & 63;
                sP[c][mm]  = Pb[(size_t)c * NN + mm];
                sWp[c][mm] = Wp[(size_t)(o0 + mm) * ldw + c];
            }
            __syncthreads();

            float acc[4][4];
#pragma unroll
            for (int mi = 0; mi < 4; ++mi) { acc[mi][0]=0.f; acc[mi][1]=0.f; acc[mi][2]=0.f; acc[mi][3]=0.f; }

#pragma unroll
            for (int c = 0; c < 4; ++c) {
                float a0 = sWp[c][of], a1 = sWp[c][of+1], a2 = sWp[c][of+2], a3 = sWp[c][of+3];
#pragma unroll
                for (int mi = 0; mi < 4; ++mi) {
                    float p = sP[c][mf + mi];
                    acc[mi][0] = fmaf(a0, p, acc[mi][0]);
                    acc[mi][1] = fmaf(a1, p, acc[mi][1]);
                    acc[mi][2] = fmaf(a2, p, acc[mi][2]);
                    acc[mi][3] = fmaf(a3, p, acc[mi][3]);
                }
            }

            if (Hprev) {
                const float* Hb = Hprev + ((size_t)b * NN + m0) * HD;
                int rr4 = tid >> 2;
                int k4  = (tid & 3) * 4;
                for (int k0 = 0; k0 < HD; k0 += 16) {
                    {
                        float4 wv = *reinterpret_cast<const float4*>(Wh + (size_t)(o0 + rr4) * ldw + k0 + k4);
                        sW[k4  ][rr4] = wv.x; sW[k4+1][rr4] = wv.y;
                        sW[k4+2][rr4] = wv.z; sW[k4+3][rr4] = wv.w;
                    }
                    {   // h written by other blocks last step -> L2-coherent load
                        float4 hv = __ldcg(reinterpret_cast<const float4*>(Hb + (size_t)rr4 * HD + k0 + k4));
                        sIn[k4  ][rr4] = hv.x; sIn[k4+1][rr4] = hv.y;
                        sIn[k4+2][rr4] = hv.z; sIn[k4+3][rr4] = hv.w;
                    }
                    __syncthreads();
#pragma unroll
                    for (int k = 0; k < 16; ++k) {
                        float4 a = *reinterpret_cast<const float4*>(&sW[k][of]);
                        float4 p = *reinterpret_cast<const float4*>(&sIn[k][mf]);
                        float pb[4] = {p.x, p.y, p.z, p.w};
#pragma unroll
                        for (int mi = 0; mi < 4; ++mi) {
                            acc[mi][0] = fmaf(a.x, pb[mi], acc[mi][0]);
                            acc[mi][1] = fmaf(a.y, pb[mi], acc[mi][1]);
                            acc[mi][2] = fmaf(a.z, pb[mi], acc[mi][2]);
                            acc[mi][3] = fmaf(a.w, pb[mi], acc[mi][3]);
                        }
                    }
                    __syncthreads();
                }
            }

            float* Ob = g_U + ((size_t)b * NN + m0 + mf) * 512 + o0 + of;
#pragma unroll
            for (int mi = 0; mi < 4; ++mi) {
                float4 v = make_float4(acc[mi][0], acc[mi][1], acc[mi][2], acc[mi][3]);
                *reinterpret_cast<float4*>(Ob + (size_t)mi * 512) = v;
            }
            __syncthreads();
        }

        grid_barrier();

        // ---------------- Phase B: gate + max over K ----------------
        {
            const float* Vt    = Vbase + (size_t)t * VSLAB;
            const float* Cprev = t ? g_c[(t-1) & 1] : nullptr;
            float* Hout = Hs + (size_t)t * SBT;
            float* Cout = g_c[t & 1];

            for (int p = blockIdx.x * 8 + warp; p < BB*NN; p += NBLK * 8) {
                int b = p >> 10, n = p & 1023;
                int mreg = 0;
                if (lane < KK)
                    mreg = g_idx[(((size_t)b*TT + t) * NN + n) * KK + lane];

                const float* Vp = Vt + ((size_t)b * NN + n) * 512 + lane * 4;
                float4 v0 = *reinterpret_cast<const float4*>(Vp);
                float4 v1 = *reinterpret_cast<const float4*>(Vp + 128);
                float4 v2 = *reinterpret_cast<const float4*>(Vp + 256);
                float4 v3 = *reinterpret_cast<const float4*>(Vp + 384);

                float4 hmax = make_float4(-1e30f,-1e30f,-1e30f,-1e30f);
                float4 cmax = hmax;
#pragma unroll 4
                for (int k = 0; k < KK; ++k) {
                    int m = __shfl_sync(0xffffffffu, mreg, k);
                    const float* Up = g_U + ((size_t)b * NN + m) * 512 + lane * 4;
                    float4 u0 = __ldcg(reinterpret_cast<const float4*>(Up));
                    float4 u1 = __ldcg(reinterpret_cast<const float4*>(Up + 128));
                    float4 u2 = __ldcg(reinterpret_cast<const float4*>(Up + 256));
                    float4 u3 = __ldcg(reinterpret_cast<const float4*>(Up + 384));
                    float4 cg = make_float4(0.f, 0.f, 0.f, 0.f);
                    if (Cprev)
                        cg = __ldcg(reinterpret_cast<const float4*>(
                                 Cprev + ((size_t)b * NN + m) * HD + lane * 4));
                    float cn, hn;
                    gate4(v0.x+u0.x, v1.x+u1.x, v2.x+u2.x, v3.x+u3.x, cg.x, cn, hn);
                    cmax.x = fmaxf(cmax.x, cn); hmax.x = fmaxf(hmax.x, hn);
                    gate4(v0.y+u0.y, v1.y+u1.y, v2.y+u2.y, v3.y+u3.y, cg.y, cn, hn);
                    cmax.y = fmaxf(cmax.y, cn); hmax.y = fmaxf(hmax.y, hn);
                    gate4(v0.z+u0.z, v1.z+u1.z, v2.z+u2.z, v3.z+u3.z, cg.z, cn, hn);
                    cmax.z = fmaxf(cmax.z, cn); hmax.z = fmaxf(hmax.z, hn);
                    gate4(v0.w+u0.w, v1.w+u1.w, v2.w+u2.w, v3.w+u3.w, cg.w, cn, hn);
                    cmax.w = fmaxf(cmax.w, cn); hmax.w = fmaxf(hmax.w, hn);
                }
                size_t o = ((size_t)b * NN + n) * HD + lane * 4;
                *reinterpret_cast<float4*>(Hout + o) = hmax;
                *reinterpret_cast<float4*>(Cout + o) = cmax;
            }
        }

        grid_barrier();
    }
}

// ---------------- output assembly ----------------
__global__ void out1_pos_kernel(const float* __restrict__ x, float* __restrict__ out) {
    int i = blockIdx.x * 256 + threadIdx.x;  // B*T*4*N = 524288
    if (i < BB*TT*4*NN) {
        int bt = i >> 12;
        int r  = i & 4095;
        out[(size_t)bt * 132 * NN + r] = x[i];
    }
}

__global__ void out1_hs_kernel(float* __restrict__ out) {
    __shared__ float tile[32][33];
    int n0 = blockIdx.x * 32, j0 = blockIdx.y * 32, bt = blockIdx.z;
    int b = bt >> 5, t = bt & 31;
    int tx = threadIdx.x, ty = threadIdx.y;
    tile[ty][tx] = g_hs1[(((size_t)t*BB + b) * NN + n0 + ty) * HD + j0 + tx];
    __syncthreads();
    out[((size_t)bt * 132 + 4 + j0 + ty) * NN + n0 + tx] = tile[tx][ty];
}

__global__ void hc_kernel(float* __restrict__ out) {
    __shared__ float th[32][33];
    __shared__ float tc[32][33];
    int n0 = blockIdx.x * 32, j0 = blockIdx.y * 32, b = blockIdx.z;
    int tx = threadIdx.x, ty = threadIdx.y;
    th[ty][tx] = g_hs1[(((size_t)(TT-1)*BB + b) * NN + n0 + ty) * HD + j0 + tx];
    tc[ty][tx] = g_c[(TT-1) & 1][((size_t)b * NN + n0 + ty) * HD + j0 + tx];
    __syncthreads();
    size_t dst = ((size_t)b * HD + j0 + ty) * NN + n0 + tx;
    out[OFF_H + dst] = th[tx][ty];
    out[OFF_C + dst] = tc[tx][ty];
}

__global__ void idxf_kernel(float* __restrict__ out) {
    int i = blockIdx.x * 256 + threadIdx.x;  // 2,097,152
    out[OFF_I + i] = (float)g_idx[i];
}

// ---------------- launch ----------------
extern "C" void kernel_launch(void* const* d_in, const int* in_sizes, int n_in,
                              void* d_out, int out_size) {
    const float* x  = (const float*)d_in[0];
    const float* w0 = (const float*)d_in[1];
    const float* b0 = (const float*)d_in[2];
    const float* w1 = (const float*)d_in[3];
    const float* b1 = (const float*)d_in[4];
    float* out = (float*)d_out;

    knn_kernel<<<dim3(4, TT, BB), 256>>>(x);
    wdiff_kernel<<<4, 128>>>(w0, w1);

    dim3 gv(8, 16, BB*TT);   // batched V gemm: 16384 blocks

    vgemm_kernel<<<gv, 256>>>(0, x, b0, w1, b1);   // V0, all t (pos only)
    layer_kernel<<<NBLK, 256>>>(0, x, w0, w1);     // layer 0: full recurrence
    vgemm_kernel<<<gv, 256>>>(1, x, b0, w1, b1);   // V1, all t (needs hs0)
    layer_kernel<<<NBLK, 256>>>(1, x, w0, w1);     // layer 1: full recurrence

    out1_pos_kernel<<<2048, 256>>>(x, out);
    out1_hs_kernel<<<dim3(32, 4, BB*TT), dim3(32, 32)>>>(out);
    hc_kernel<<<dim3(32, 4, BB), dim3(32, 32)>>>(out);
    idxf_kernel<<<8192, 256>>>(out);
}